// round 14
// baseline (speedup 1.0000x reference)
#include <cuda_runtime.h>
#include <cuda_bf16.h>
#include <cstdint>

// Problem shape: A [64, 2048, 64], B [64, 64, 2048], out [64, 2048, 2048] (batch=4*16 flattened)
#define NBATCH 64
#define SDIM   2048
#define TDIM   2048
#define DDIM   64
#define NA_EL  (NBATCH * SDIM * DDIM)   // 8388608
#define NB_EL  (NBATCH * DDIM * TDIM)   // 8388608
#define PREP_BLOCKS 592                 // exactly 4 per SM (148 SMs) -> all co-resident
#define NGROUPS 2048                    // super-groups: (b, m-tile, n-half), 8 tiles each
#define GEMM_GRID 296                   // 2 CTAs per SM

// ---- device-global state (scratch; no allocations allowed) ----
__device__ float g_pmin[2][PREP_BLOCKS], g_pmax[2][PREP_BLOCKS];
__device__ float g_scale;
__device__ int   g_arrive, g_done;      // grid barrier counters (self-resetting)
__device__ __nv_bfloat16 g_Aq[NA_EL];
__device__ __nv_bfloat16 g_Bq[NB_EL];

// ---- fused prologue: minmax partials -> grid barrier -> params -> quant ----
// One launch (saves 2 launch boundaries + L2 reuse of input tails). Grid is
// exactly co-resident (592 blocks of 256 on 148 SMs) so the spin barrier cannot
// deadlock. Counters self-reset for deterministic graph replay.
__global__ void __launch_bounds__(256) k_prep(const float* __restrict__ A,
                                              const float* __restrict__ B) {
    const int tid = threadIdx.x;
    const int bid = blockIdx.x;
    const int gid = bid * 256 + tid;
    const int STRIDE = PREP_BLOCKS * 256;
    const int n4 = NA_EL / 4;
    const float4* A4 = (const float4*)A;
    const float4* B4 = (const float4*)B;

    // ---- phase 1: interleaved minmax scan of A and B (2x MLP) ----
    float mna = 0.0f, mxa = 0.0f, mnb = 0.0f, mxb = 0.0f;
    for (int i = gid; i < n4; i += STRIDE) {
        float4 a = A4[i];
        float4 b = B4[i];
        mna = fminf(mna, fminf(fminf(a.x, a.y), fminf(a.z, a.w)));
        mxa = fmaxf(mxa, fmaxf(fmaxf(a.x, a.y), fmaxf(a.z, a.w)));
        mnb = fminf(mnb, fminf(fminf(b.x, b.y), fminf(b.z, b.w)));
        mxb = fmaxf(mxb, fmaxf(fmaxf(b.x, b.y), fmaxf(b.z, b.w)));
    }
    #pragma unroll
    for (int o = 16; o > 0; o >>= 1) {
        mna = fminf(mna, __shfl_xor_sync(0xffffffffu, mna, o));
        mxa = fmaxf(mxa, __shfl_xor_sync(0xffffffffu, mxa, o));
        mnb = fminf(mnb, __shfl_xor_sync(0xffffffffu, mnb, o));
        mxb = fmaxf(mxb, __shfl_xor_sync(0xffffffffu, mxb, o));
    }
    __shared__ float sred[4][8];
    __shared__ float s_dA, s_zA, s_dB, s_zB;
    int wid = tid >> 5, lane = tid & 31;
    if (lane == 0) { sred[0][wid] = mna; sred[1][wid] = mxa; sred[2][wid] = mnb; sred[3][wid] = mxb; }
    __syncthreads();
    if (tid == 0) {
        float a0 = sred[0][0], a1 = sred[1][0], b0 = sred[2][0], b1 = sred[3][0];
        #pragma unroll
        for (int w = 1; w < 8; w++) {
            a0 = fminf(a0, sred[0][w]); a1 = fmaxf(a1, sred[1][w]);
            b0 = fminf(b0, sred[2][w]); b1 = fmaxf(b1, sred[3][w]);
        }
        g_pmin[0][bid] = a0; g_pmax[0][bid] = a1;
        g_pmin[1][bid] = b0; g_pmax[1][bid] = b1;
        __threadfence();                       // partials visible before arrival
        atomicAdd(&g_arrive, 1);
    }

    // ---- grid barrier (all 592 blocks co-resident by construction) ----
    if (tid == 0) {
        while (atomicAdd(&g_arrive, 0) < PREP_BLOCKS) { }
        __threadfence();                       // acquire: partials from all blocks
    }
    __syncthreads();

    // ---- phase 2: reduce all partials -> quant params (every block, identical) ----
    float rmA = 1e30f, rMA = -1e30f, rmB = 1e30f, rMB = -1e30f;
    for (int idx = tid; idx < PREP_BLOCKS; idx += 256) {
        rmA = fminf(rmA, g_pmin[0][idx]); rMA = fmaxf(rMA, g_pmax[0][idx]);
        rmB = fminf(rmB, g_pmin[1][idx]); rMB = fmaxf(rMB, g_pmax[1][idx]);
    }
    #pragma unroll
    for (int o = 16; o > 0; o >>= 1) {
        rmA = fminf(rmA, __shfl_xor_sync(0xffffffffu, rmA, o));
        rMA = fmaxf(rMA, __shfl_xor_sync(0xffffffffu, rMA, o));
        rmB = fminf(rmB, __shfl_xor_sync(0xffffffffu, rmB, o));
        rMB = fmaxf(rMB, __shfl_xor_sync(0xffffffffu, rMB, o));
    }
    __syncthreads();   // sred reuse
    if (lane == 0) { sred[0][wid] = rmA; sred[1][wid] = rMA; sred[2][wid] = rmB; sred[3][wid] = rMB; }
    __syncthreads();
    if (tid == 0) {
        float minA = sred[0][0], maxA = sred[1][0], minB = sred[2][0], maxB = sred[3][0];
        #pragma unroll
        for (int w = 1; w < 8; w++) {
            minA = fminf(minA, sred[0][w]); maxA = fmaxf(maxA, sred[1][w]);
            minB = fminf(minB, sred[2][w]); maxB = fmaxf(maxB, sred[3][w]);
        }
        float dA = fmaxf(__fdiv_rn(maxA - minA, 255.0f), 1e-8f);
        float dB = fmaxf(__fdiv_rn(maxB - minB, 255.0f), 1e-8f);
        s_dA = dA; s_zA = rintf(__fdiv_rn(-minA, dA));
        s_dB = dB; s_zB = rintf(__fdiv_rn(-minB, dB));
        if (bid == 0) g_scale = dA * dB;
    }
    __syncthreads();
    const float dA = s_dA, zA = s_zA, dB = s_dB, zB = s_zB;

    // ---- phase 3: quantize both tensors (INTEGER-valued bf16; exact) ----
    uint2* oa = (uint2*)g_Aq;
    uint2* ob = (uint2*)g_Bq;
    for (int i = gid; i < n4; i += STRIDE) {
        float4 a = A4[i];
        float4 b = B4[i];
        float qa0 = fminf(fmaxf(rintf(__fdiv_rn(a.x, dA)) + zA, 0.0f), 255.0f) - zA;
        float qa1 = fminf(fmaxf(rintf(__fdiv_rn(a.y, dA)) + zA, 0.0f), 255.0f) - zA;
        float qa2 = fminf(fmaxf(rintf(__fdiv_rn(a.z, dA)) + zA, 0.0f), 255.0f) - zA;
        float qa3 = fminf(fmaxf(rintf(__fdiv_rn(a.w, dA)) + zA, 0.0f), 255.0f) - zA;
        float qb0 = fminf(fmaxf(rintf(__fdiv_rn(b.x, dB)) + zB, 0.0f), 255.0f) - zB;
        float qb1 = fminf(fmaxf(rintf(__fdiv_rn(b.y, dB)) + zB, 0.0f), 255.0f) - zB;
        float qb2 = fminf(fmaxf(rintf(__fdiv_rn(b.z, dB)) + zB, 0.0f), 255.0f) - zB;
        float qb3 = fminf(fmaxf(rintf(__fdiv_rn(b.w, dB)) + zB, 0.0f), 255.0f) - zB;
        __nv_bfloat162 pa0 = __floats2bfloat162_rn(qa0, qa1);
        __nv_bfloat162 pa1 = __floats2bfloat162_rn(qa2, qa3);
        __nv_bfloat162 pb0 = __floats2bfloat162_rn(qb0, qb1);
        __nv_bfloat162 pb1 = __floats2bfloat162_rn(qb2, qb3);
        uint2 ua, ub;
        ua.x = *(uint32_t*)&pa0; ua.y = *(uint32_t*)&pa1;
        ub.x = *(uint32_t*)&pb0; ub.y = *(uint32_t*)&pb1;
        oa[i] = ua;
        ob[i] = ub;
    }

    // ---- counter reset for next graph replay (deterministic) ----
    if (tid == 0) {
        int d = atomicAdd(&g_done, 1);
        if (d == PREP_BLOCKS - 1) {       // last block out resets both counters
            atomicExch(&g_arrive, 0);
            atomicExch(&g_done, 0);
        }
    }
}

// ---- pass 2: persistent GEMM, CTA tile 128x128, A-reuse grouping (R13 core) ----
// Super-group u = (b, m, n-half): 8 consecutive n-tiles share one A tile.
// A loaded ONCE per group (double-buffered by group parity); B keeps the
// 3-stage prefetch-depth-2 pipeline with a single barrier per tile.
#define SA_ROWS 128
#define SA_COLS 72     // 64 + 8 pad (16B row shift -> no LDSM conflicts)
#define SB_ROWS 64
#define SB_COLS 136    // 128 + 8 pad
#define SA_BYTES (SA_ROWS * SA_COLS * 2)       // 18432
#define SB_BYTES (SB_ROWS * SB_COLS * 2)       // 17408
#define NSTAGE 3
#define SMEM_DYN (2 * SA_BYTES + NSTAGE * SB_BYTES)   // 89088 B (2 CTAs/SM)

__device__ __forceinline__ void cpa16(void* dst, const void* src) {
    uint32_t d = (uint32_t)__cvta_generic_to_shared(dst);
    asm volatile("cp.async.cg.shared.global [%0], [%1], 16;" :: "r"(d), "l"(src));
}

__global__ void __launch_bounds__(256, 2) k_gemm(float* __restrict__ out) {
    extern __shared__ char smem_raw[];

    const int tid = threadIdx.x;
    const int bid = blockIdx.x;
    const int warp = tid >> 5, lane = tid & 31;
    const int wm = warp >> 2;      // 0..1 -> 64 rows each
    const int wn = warp & 3;       // 0..3 -> 32 cols each

    const int ar = tid >> 3, ac = (tid & 7) * 8;          // A rows ar+{0,32,64,96}
    const int br = tid >> 4, bc = (tid & 15) * 8;         // B rows br+{0,16,32,48}

    auto bufA = [&](int p) -> __nv_bfloat16 (*)[SA_COLS] {
        return (__nv_bfloat16 (*)[SA_COLS])(smem_raw + p * SA_BYTES);
    };
    auto stageB = [&](int st) -> __nv_bfloat16 (*)[SB_COLS] {
        return (__nv_bfloat16 (*)[SB_COLS])(smem_raw + 2 * SA_BYTES + st * SB_BYTES);
    };

    // local tile i -> group k = i>>3 (u = bid + k*GRID), j = i&7
    // u decode: b = u>>5, m-tile = (u>>1)&15, n-half = u&1
    const int ngroups = (NGROUPS - bid + GEMM_GRID - 1) / GEMM_GRID;
    const int L = ngroups * 8;

    // commit ONE cp.async group for local tile i: B(i) (+ A(u) when i%8==0)
    auto load_group = [&](int i) {
        int k = i >> 3, j = i & 7;
        int u = bid + k * GEMM_GRID;
        int b  = u >> 5;
        int m0 = ((u >> 1) & 15) * 128;
        int n0 = (u & 1) * 1024 + j * 128;
        if ((i & 7) == 0) {
            const __nv_bfloat16* Ab = g_Aq + (size_t)b * SDIM * DDIM + (size_t)m0 * DDIM;
            __nv_bfloat16 (*sA)[SA_COLS] = bufA(k & 1);
            #pragma unroll
            for (int it = 0; it < 4; it++)
                cpa16(&sA[ar + it * 32][ac], Ab + (ar + it * 32) * DDIM + ac);
        }
        const __nv_bfloat16* Bb = g_Bq + (size_t)b * DDIM * TDIM + n0;
        __nv_bfloat16 (*sB)[SB_COLS] = stageB(i % 3);
        #pragma unroll
        for (int it = 0; it < 4; it++)
            cpa16(&sB[br + it * 16][bc], Bb + (size_t)(br + it * 16) * TDIM + bc);
        asm volatile("cp.async.commit_group;");
    };

    const float s = g_scale;

    load_group(0);
    if (L > 1) load_group(1);

    for (int i = 0; i < L; i++) {
        if (i + 1 < L) {
            asm volatile("cp.async.wait_group 1;");   // this tile's group done
        } else {
            asm volatile("cp.async.wait_group 0;");
        }
        __syncthreads();   // single barrier per iteration

        const int k = i >> 3, j = i & 7;
        const int u = bid + k * GEMM_GRID;
        const int b  = u >> 5;
        const int m0 = ((u >> 1) & 15) * 128;
        const int n0 = (u & 1) * 1024 + j * 128;

        __nv_bfloat16 (*sA)[SA_COLS] = bufA(k & 1);
        __nv_bfloat16 (*sB)[SB_COLS] = stageB(i % 3);

        float acc[4][4][4];
        #pragma unroll
        for (int mi = 0; mi < 4; mi++)
            #pragma unroll
            for (int ni = 0; ni < 4; ni++)
                #pragma unroll
                for (int q = 0; q < 4; q++) acc[mi][ni][q] = 0.0f;

        #pragma unroll
        for (int ks = 0; ks < 4; ks++) {
            const int k0 = ks * 16;
            uint32_t af[4][4];
            #pragma unroll
            for (int mi = 0; mi < 4; mi++) {
                int r = wm * 64 + mi * 16 + (lane & 15);
                int c = k0 + (lane >> 4) * 8;
                uint32_t addr = (uint32_t)__cvta_generic_to_shared(&sA[r][c]);
                asm volatile(
                    "ldmatrix.sync.aligned.m8n8.x4.shared.b16 {%0,%1,%2,%3}, [%4];"
                    : "=r"(af[mi][0]), "=r"(af[mi][1]), "=r"(af[mi][2]), "=r"(af[mi][3])
                    : "r"(addr));
            }
            uint32_t bf[4][2];
            #pragma unroll
            for (int nj = 0; nj < 2; nj++) {
                int r = k0 + (lane & 7) + ((lane >> 3) & 1) * 8;
                int c = wn * 32 + nj * 16 + (lane >> 4) * 8;
                uint32_t addr = (uint32_t)__cvta_generic_to_shared(&sB[r][c]);
                uint32_t t0, t1, t2, t3;
                asm volatile(
                    "ldmatrix.sync.aligned.m8n8.x4.trans.shared.b16 {%0,%1,%2,%3}, [%4];"
                    : "=r"(t0), "=r"(t1), "=r"(t2), "=r"(t3)
                    : "r"(addr));
                bf[nj * 2 + 0][0] = t0; bf[nj * 2 + 0][1] = t1;
                bf[nj * 2 + 1][0] = t2; bf[nj * 2 + 1][1] = t3;
            }
            #pragma unroll
            for (int mi = 0; mi < 4; mi++)
                #pragma unroll
                for (int ni = 0; ni < 4; ni++) {
                    asm volatile(
                        "mma.sync.aligned.m16n8k16.row.col.f32.bf16.bf16.f32 "
                        "{%0,%1,%2,%3}, {%4,%5,%6,%7}, {%8,%9}, {%0,%1,%2,%3};"
                        : "+f"(acc[mi][ni][0]), "+f"(acc[mi][ni][1]),
                          "+f"(acc[mi][ni][2]), "+f"(acc[mi][ni][3])
                        : "r"(af[mi][0]), "r"(af[mi][1]), "r"(af[mi][2]), "r"(af[mi][3]),
                          "r"(bf[ni][0]), "r"(bf[ni][1]));
                }
        }

        // epilogue stores (drain while loads for i+2 stream and next iter computes)
        {
            float* ob = out + (size_t)b * SDIM * TDIM;
            #pragma unroll
            for (int mi = 0; mi < 4; mi++) {
                #pragma unroll
                for (int ni = 0; ni < 4; ni++) {
                    int r = m0 + wm * 64 + mi * 16 + (lane >> 2);
                    int c = n0 + wn * 32 + ni * 8 + (lane & 3) * 2;
                    float2 v0 = make_float2(acc[mi][ni][0] * s, acc[mi][ni][1] * s);
                    float2 v1 = make_float2(acc[mi][ni][2] * s, acc[mi][ni][3] * s);
                    *(float2*)&ob[(size_t)r * TDIM + c]       = v0;
                    *(float2*)&ob[(size_t)(r + 8) * TDIM + c] = v1;
                }
            }
        }

        // prefetch local tile i+2 (B stage (i+2)%3 != current/next; A goes to
        // the idle parity buffer — races excluded by the top barrier)
        if (i + 2 < L) load_group(i + 2);
    }
}

extern "C" void kernel_launch(void* const* d_in, const int* in_sizes, int n_in,
                              void* d_out, int out_size) {
    const float* A = (const float*)d_in[0];
    const float* B = (const float*)d_in[1];
    float* out = (float*)d_out;

    cudaFuncSetAttribute(k_gemm, cudaFuncAttributeMaxDynamicSharedMemorySize, SMEM_DYN);

    k_prep<<<PREP_BLOCKS, 256>>>(A, B);
    k_gemm<<<GEMM_GRID, 256, SMEM_DYN>>>(out);
}